// round 7
// baseline (speedup 1.0000x reference)
#include <cuda_runtime.h>
#include <cuda_fp16.h>
#include <math.h>
#include <stdint.h>

// Problem constants
constexpr int T_  = 4096;
constexpr int E_  = 8;
constexpr int H_  = 1024;
constexpr int I_  = 2048;
constexpr int CAP = 4096;

// ---------------------------------------------------------------------------
// Scratch (device globals)
// ---------------------------------------------------------------------------
__device__ int   g_count[E_];
__device__ int   g_tok[E_ * CAP];
__device__ int   g_slot[T_ * 2];
__device__ float g_wt[T_ * 2];

__device__ __half g_w13h[(size_t)E_ * 2 * I_ * H_];  // plain convert of w13 (no permute)
__device__ __half g_w2h [(size_t)E_ * H_ * I_];
__device__ __half g_xh  [(size_t)T_ * H_];
__device__ __half g_xl  [(size_t)T_ * H_];
__device__ __half g_hh  [(size_t)E_ * CAP * I_];
__device__ __half g_hl  [(size_t)E_ * CAP * I_];
__device__ float  g_y   [(size_t)E_ * CAP * H_];

// ---------------------------------------------------------------------------
// helpers
// ---------------------------------------------------------------------------
__device__ __forceinline__ uint32_t smem_u32(const void* p) {
    uint32_t a;
    asm("{ .reg .u64 t; cvta.to.shared.u64 t, %1; cvt.u32.u64 %0, t; }" : "=r"(a) : "l"(p));
    return a;
}
__device__ __forceinline__ void cp_async16(uint32_t dst, const void* src, int src_bytes) {
    asm volatile("cp.async.cg.shared.global [%0], [%1], 16, %2;"
                 :: "r"(dst), "l"(src), "r"(src_bytes));
}
#define CP_COMMIT() asm volatile("cp.async.commit_group;" ::: "memory")
#define CP_WAIT1()  asm volatile("cp.async.wait_group 1;" ::: "memory")

__device__ __forceinline__ void ldm_x4(uint32_t addr, uint32_t* r) {
    asm volatile("ldmatrix.sync.aligned.m8n8.x4.shared.b16 {%0,%1,%2,%3}, [%4];"
                 : "=r"(r[0]), "=r"(r[1]), "=r"(r[2]), "=r"(r[3]) : "r"(addr));
}
__device__ __forceinline__ void mma16816(float* c, const uint32_t* a, const uint32_t* b) {
    asm volatile("mma.sync.aligned.m16n8k16.row.col.f32.f16.f16.f32 "
                 "{%0,%1,%2,%3}, {%4,%5,%6,%7}, {%8,%9}, {%0,%1,%2,%3};"
                 : "+f"(c[0]), "+f"(c[1]), "+f"(c[2]), "+f"(c[3])
                 : "r"(a[0]), "r"(a[1]), "r"(a[2]), "r"(a[3]), "r"(b[0]), "r"(b[1]));
}

// ---------------------------------------------------------------------------
// router / init / combine
// ---------------------------------------------------------------------------
__global__ void init_kernel() { if (threadIdx.x < E_) g_count[threadIdx.x] = 0; }

__global__ void router_kernel(const float* __restrict__ logits) {
    int t = blockIdx.x * blockDim.x + threadIdx.x;
    if (t >= T_) return;
    float l[E_];
#pragma unroll
    for (int e = 0; e < E_; e++) l[e] = logits[t * E_ + e];
    int b0 = 0; float m0 = l[0];
#pragma unroll
    for (int e = 1; e < E_; e++) if (l[e] > m0) { m0 = l[e]; b0 = e; }
    int b1 = -1; float m1 = -3.0e38f;
#pragma unroll
    for (int e = 0; e < E_; e++) if (e != b0 && l[e] > m1) { m1 = l[e]; b1 = e; }
    float w0 = 1.0f / (1.0f + expf(m1 - m0));
    float w1 = 1.0f - w0;
    int p0 = atomicAdd(&g_count[b0], 1);
    g_tok[b0 * CAP + p0] = t;  g_slot[2 * t + 0] = b0 * CAP + p0;  g_wt[2 * t + 0] = w0;
    int p1 = atomicAdd(&g_count[b1], 1);
    g_tok[b1 * CAP + p1] = t;  g_slot[2 * t + 1] = b1 * CAP + p1;  g_wt[2 * t + 1] = w1;
}

__global__ void combine_kernel(float* __restrict__ out) {
    int t = blockIdx.x;
    int   s0 = g_slot[2 * t + 0], s1 = g_slot[2 * t + 1];
    float w0 = g_wt [2 * t + 0], w1 = g_wt [2 * t + 1];
    const float* y0 = g_y + (size_t)s0 * H_;
    const float* y1 = g_y + (size_t)s1 * H_;
    float* o = out + (size_t)t * H_;
    for (int j = threadIdx.x; j < H_; j += blockDim.x)
        o[j] = w0 * y0[j] + w1 * y1[j];
}

// ---------------------------------------------------------------------------
// conversion kernels
// ---------------------------------------------------------------------------
// fp32 -> fp16 hi/lo split (x only)
__global__ void split_kernel(const float* __restrict__ s, __half* __restrict__ h,
                             __half* __restrict__ l, size_t n4) {
    size_t i = blockIdx.x * (size_t)blockDim.x + threadIdx.x;
    if (i >= n4) return;
    float4 v = ((const float4*)s)[i];
    __half h0 = __float2half_rn(v.x), h1 = __float2half_rn(v.y),
           h2 = __float2half_rn(v.z), h3 = __float2half_rn(v.w);
    ((__half2*)h)[2 * i]     = __halves2half2(h0, h1);
    ((__half2*)h)[2 * i + 1] = __halves2half2(h2, h3);
    ((__half2*)l)[2 * i]     = __halves2half2(__float2half_rn(v.x - __half2float(h0)),
                                              __float2half_rn(v.y - __half2float(h1)));
    ((__half2*)l)[2 * i + 1] = __halves2half2(__float2half_rn(v.z - __half2float(h2)),
                                              __float2half_rn(v.w - __half2float(h3)));
}

// fp32 -> fp16 (hi only), linear
__global__ void convert_kernel(const float* __restrict__ s, __half* __restrict__ h, size_t n4) {
    size_t i = blockIdx.x * (size_t)blockDim.x + threadIdx.x;
    if (i >= n4) return;
    float4 v = ((const float4*)s)[i];
    ((__half2*)h)[2 * i]     = __halves2half2(__float2half_rn(v.x), __float2half_rn(v.y));
    ((__half2*)h)[2 * i + 1] = __halves2half2(__float2half_rn(v.z), __float2half_rn(v.w));
}

// ---------------------------------------------------------------------------
// GEMM1: 128x256 tile, 256 threads, 1 CTA/SM.
// C[tile] = x[gathered 128 rows, K=H] @ w13[e]^T with on-the-fly gate/up
// column interleave (B tile col c -> w13 row c/2 (even: gate) or I+c/2 (odd: up)).
// Dual pass (xh*B + xl*B) on shared B frags; fused silu(g)*u epilogue ->
// hh/hl (hi/lo split) via SMEM staging for coalesced stores.
// ---------------------------------------------------------------------------
__global__ void __launch_bounds__(256, 1)
moe_gemm1(const __half* __restrict__ Ah, const __half* __restrict__ Al,
          const __half* __restrict__ Bh,
          __half* __restrict__ Hh, __half* __restrict__ Hl)
{
    constexpr int KD = H_;            // 1024
    constexpr int CHUNKS = KD / 64;   // 16
    constexpr uint32_t STAGE = 65536; // Ah 16K + Al 16K + B 32K

    const int e    = blockIdx.z;
    const int cnt  = g_count[e];
    const int row0 = blockIdx.y * 128;
    if (row0 >= cnt) return;
    const int col0 = blockIdx.x * 256;   // B-column base (interleaved index)

    extern __shared__ char smem[];
    const uint32_t sb = smem_u32(smem);

    const int tid  = threadIdx.x;
    const int wid  = tid >> 5;
    const int lane = tid & 31;
    const int warp_m = wid & 3;          // 4 warps over M (32 rows each)
    const int warp_n = wid >> 2;         // 2 warps over N (128 cols each)

    const int crow  = tid >> 3;          // 0..31
    const int ckb   = (tid & 7) * 16;
    const int chalf = (tid & 7) * 8;

    uint32_t aoff[4]; int avalid[4]; uint32_t dstoA[4];
#pragma unroll
    for (int i = 0; i < 4; i++) {
        int r = crow + i * 32;
        int gr = row0 + r;
        avalid[i] = (gr < cnt) ? 16 : 0;
        aoff[i]   = (gr < cnt) ? (uint32_t)g_tok[e * CAP + gr] * KD : 0;
        dstoA[i]  = (uint32_t)(r * 128 + (ckb ^ ((r & 7) << 4)));
    }
    uint32_t boff[8]; uint32_t dstoB[8];
#pragma unroll
    for (int i = 0; i < 8; i++) {
        int r = crow + i * 32;           // 0..255
        int c = col0 + r;                // interleaved column
        int grow = (c & 1) ? (I_ + (c >> 1)) : (c >> 1);
        boff[i]  = ((uint32_t)e * (2 * I_) + (uint32_t)grow) * KD;
        dstoB[i] = (uint32_t)(r * 128 + (ckb ^ ((r & 7) << 4)));
    }

    auto issue = [&](int c) {
        const uint32_t sA = sb + (c & 1) * STAGE;
        const uint32_t sL = sA + 16384;
        const uint32_t sB = sA + 32768;
        const uint32_t kofs = (uint32_t)c * 64 + chalf;
#pragma unroll
        for (int i = 0; i < 4; i++)
            cp_async16(sA + dstoA[i], Ah + aoff[i] + kofs, avalid[i]);
#pragma unroll
        for (int i = 0; i < 4; i++)
            cp_async16(sL + dstoA[i], Al + aoff[i] + kofs, avalid[i]);
#pragma unroll
        for (int i = 0; i < 8; i++)
            cp_async16(sB + dstoB[i], Bh + boff[i] + kofs, 16);
        CP_COMMIT();
    };

    float acc[2][16][4];
#pragma unroll
    for (int t = 0; t < 2; t++)
#pragma unroll
        for (int n = 0; n < 16; n++)
#pragma unroll
            for (int q = 0; q < 4; q++) acc[t][n][q] = 0.0f;

    issue(0);

    const int g  = lane >> 3;
    const int rl = lane & 7;
    const int a_row  = warp_m * 32 + (g & 1) * 8 + rl;
    const int a_byte = (g >> 1) * 16;
    const int b_row  = warp_n * 128 + (g & 2) * 4 + rl;
    const int b_byte = (g & 1) * 16;

#pragma unroll 1
    for (int it = 0; it < CHUNKS; it++) {
        if (it + 1 < CHUNKS) issue(it + 1);
        CP_WAIT1();
        __syncthreads();

        const uint32_t sA = sb + (it & 1) * STAGE;
        const uint32_t sL = sA + 16384;
        const uint32_t sB = sA + 32768;

#pragma unroll
        for (int ks = 0; ks < 4; ks++) {
            const int kb = ks * 32;
            uint32_t af[2][4], al[2][4];
#pragma unroll
            for (int t = 0; t < 2; t++) {
                int row = a_row + t * 16;
                uint32_t sw = row * 128 + ((a_byte + kb) ^ ((row & 7) << 4));
                ldm_x4(sA + sw, af[t]);
                ldm_x4(sL + sw, al[t]);
            }
#pragma unroll
            for (int q = 0; q < 8; q++) {
                int row = b_row + q * 16;
                uint32_t addr = sB + row * 128 + ((b_byte + kb) ^ ((row & 7) << 4));
                uint32_t r4[4];
                ldm_x4(addr, r4);
                uint32_t b0[2] = { r4[0], r4[1] };
                uint32_t b1[2] = { r4[2], r4[3] };
#pragma unroll
                for (int t = 0; t < 2; t++) {
                    mma16816(acc[t][2 * q],     af[t], b0);
                    mma16816(acc[t][2 * q + 1], af[t], b1);
                    mma16816(acc[t][2 * q],     al[t], b0);
                    mma16816(acc[t][2 * q + 1], al[t], b1);
                }
            }
        }
        __syncthreads();
    }

    // ------------------------------ epilogue ------------------------------
    // Warp tile: rows warp_m*32..+32, h-cols (col0/2 + warp_n*64)..+64.
    // Stage hi/lo in warp-private SMEM (32 rows x 128B each), store 16B-coalesced.
    const int qr = lane >> 2;
    const int qc = lane & 3;
    char* wreg = smem + wid * 8192;   // [0,4096)=hi, [4096,8192)=lo

#pragma unroll
    for (int t = 0; t < 2; t++) {
#pragma unroll
        for (int n = 0; n < 16; n++) {
            int cl = (n * 4 + qc) * 2;
            {
                float gg = acc[t][n][0], uu = acc[t][n][1];
                float hv = gg / (1.0f + expf(-gg)) * uu;
                __half hi = __float2half_rn(hv);
                int rb = (t * 16 + qr) * 128;
                *(__half*)(wreg + rb + cl)        = hi;
                *(__half*)(wreg + 4096 + rb + cl) = __float2half_rn(hv - __half2float(hi));
            }
            {
                float gg = acc[t][n][2], uu = acc[t][n][3];
                float hv = gg / (1.0f + expf(-gg)) * uu;
                __half hi = __float2half_rn(hv);
                int rb = (t * 16 + qr + 8) * 128;
                *(__half*)(wreg + rb + cl)        = hi;
                *(__half*)(wreg + 4096 + rb + cl) = __float2half_rn(hv - __half2float(hi));
            }
        }
    }
    __syncwarp();
    const size_t pbase = (size_t)(col0 >> 1) + warp_n * 64;
#pragma unroll
    for (int p = 0; p < 8; p++) {
        int row_local = p * 4 + (lane >> 3);
        int c16 = lane & 7;
        int r = row0 + warp_m * 32 + row_local;
        if (r < cnt) {
            uint4 vh = *(uint4*)(wreg + row_local * 128 + c16 * 16);
            uint4 vl = *(uint4*)(wreg + 4096 + row_local * 128 + c16 * 16);
            size_t o = ((size_t)e * CAP + r) * I_ + pbase + c16 * 8;
            *(uint4*)(Hh + o) = vh;
            *(uint4*)(Hl + o) = vl;
        }
    }
}

// ---------------------------------------------------------------------------
// GEMM2: 128x128 tile, 256 threads, 2 CTA/SM (round-5 proven config).
// Dual pass (hh*w2 + hl*w2) on shared B frags, fp32 output.
// ---------------------------------------------------------------------------
__global__ void __launch_bounds__(256, 2)
moe_gemm2(const __half* __restrict__ Ah, const __half* __restrict__ Al,
          const __half* __restrict__ Bh, float* __restrict__ Y)
{
    constexpr int KD = I_;            // 2048
    constexpr int NTOT = H_;          // 1024
    constexpr int CHUNKS = KD / 64;   // 32
    constexpr uint32_t STAGE = 49152; // Ah 16K + Al 16K + B 16K

    const int e    = blockIdx.z;
    const int cnt  = g_count[e];
    const int row0 = blockIdx.y * 128;
    if (row0 >= cnt) return;
    const int col0 = blockIdx.x * 128;

    extern __shared__ char smem[];
    const uint32_t sb = smem_u32(smem);

    const int tid  = threadIdx.x;
    const int wid  = tid >> 5;
    const int lane = tid & 31;
    const int warp_m = wid & 3;
    const int warp_n = wid >> 2;

    const int crow  = tid >> 3;
    const int ckb   = (tid & 7) * 16;
    const int chalf = (tid & 7) * 8;

    size_t aoff[4]; int avalid[4];
    size_t boff[4];
    uint32_t dsto[4];
#pragma unroll
    for (int i = 0; i < 4; i++) {
        int r = crow + i * 32;
        int gr = row0 + r;
        avalid[i] = 16;
        aoff[i] = (size_t)(e * CAP + gr) * KD;
        boff[i] = ((size_t)e * NTOT + col0 + r) * (size_t)KD;
        dsto[i] = (uint32_t)(r * 128 + (ckb ^ ((r & 7) << 4)));
    }

    auto issue = [&](int c) {
        const uint32_t sA = sb + (c & 1) * STAGE;
        const uint32_t sL = sA + 16384;
        const uint32_t sB = sA + 32768;
        const size_t kofs = (size_t)c * 64 + chalf;
#pragma unroll
        for (int i = 0; i < 4; i++)
            cp_async16(sA + dsto[i], Ah + aoff[i] + kofs, avalid[i]);
#pragma unroll
        for (int i = 0; i < 4; i++)
            cp_async16(sL + dsto[i], Al + aoff[i] + kofs, avalid[i]);
#pragma unroll
        for (int i = 0; i < 4; i++)
            cp_async16(sB + dsto[i], Bh + boff[i] + kofs, 16);
        CP_COMMIT();
    };

    float acc[2][8][4];
#pragma unroll
    for (int t = 0; t < 2; t++)
#pragma unroll
        for (int n = 0; n < 8; n++)
#pragma unroll
            for (int q = 0; q < 4; q++) acc[t][n][q] = 0.0f;

    issue(0);

    const int g  = lane >> 3;
    const int rl = lane & 7;
    const int a_row  = warp_m * 32 + (g & 1) * 8 + rl;
    const int a_byte = (g >> 1) * 16;
    const int b_row  = warp_n * 64 + (g & 2) * 4 + rl;
    const int b_byte = (g & 1) * 16;

#pragma unroll 1
    for (int it = 0; it < CHUNKS; it++) {
        if (it + 1 < CHUNKS) issue(it + 1);
        CP_WAIT1();
        __syncthreads();

        const uint32_t sA = sb + (it & 1) * STAGE;
        const uint32_t sL = sA + 16384;
        const uint32_t sB = sA + 32768;

#pragma unroll
        for (int ks = 0; ks < 4; ks++) {
            const int kb = ks * 32;
            uint32_t af[2][4], al[2][4];
#pragma unroll
            for (int t = 0; t < 2; t++) {
                int row = a_row + t * 16;
                uint32_t sw = row * 128 + ((a_byte + kb) ^ ((row & 7) << 4));
                ldm_x4(sA + sw, af[t]);
                ldm_x4(sL + sw, al[t]);
            }
            uint32_t bf[8][2];
#pragma unroll
            for (int q = 0; q < 4; q++) {
                int row = b_row + q * 16;
                uint32_t addr = sB + row * 128 + ((b_byte + kb) ^ ((row & 7) << 4));
                uint32_t r4[4];
                ldm_x4(addr, r4);
                bf[2 * q][0] = r4[0]; bf[2 * q][1] = r4[1];
                bf[2 * q + 1][0] = r4[2]; bf[2 * q + 1][1] = r4[3];
            }
#pragma unroll
            for (int t = 0; t < 2; t++)
#pragma unroll
                for (int n = 0; n < 8; n++) {
                    mma16816(acc[t][n], af[t], bf[n]);
                    mma16816(acc[t][n], al[t], bf[n]);
                }
        }
        __syncthreads();
    }

    const int qr = lane >> 2;
    const int qc = lane & 3;
#pragma unroll
    for (int t = 0; t < 2; t++) {
        int r_lo = row0 + warp_m * 32 + t * 16 + qr;
        int r_hi = r_lo + 8;
#pragma unroll
        for (int n = 0; n < 8; n++) {
            int col = col0 + warp_n * 64 + n * 8 + 2 * qc;
            if (r_lo < cnt)
                *(float2*)&Y[((size_t)e * CAP + r_lo) * NTOT + col] =
                    make_float2(acc[t][n][0], acc[t][n][1]);
            if (r_hi < cnt)
                *(float2*)&Y[((size_t)e * CAP + r_hi) * NTOT + col] =
                    make_float2(acc[t][n][2], acc[t][n][3]);
        }
    }
}

// ---------------------------------------------------------------------------
// launch
// ---------------------------------------------------------------------------
extern "C" void kernel_launch(void* const* d_in, const int* in_sizes, int n_in,
                              void* d_out, int out_size)
{
    const float* x      = (const float*)d_in[0];
    const float* logits = (const float*)d_in[1];
    const float* w13    = (const float*)d_in[2];
    const float* w2     = (const float*)d_in[3];
    float* out = (float*)d_out;

    __half *w13h, *w2h, *xh, *xl, *hh, *hl;
    float* y;
    cudaGetSymbolAddress((void**)&w13h, g_w13h);
    cudaGetSymbolAddress((void**)&w2h,  g_w2h);
    cudaGetSymbolAddress((void**)&xh,   g_xh);
    cudaGetSymbolAddress((void**)&xl,   g_xl);
    cudaGetSymbolAddress((void**)&hh,   g_hh);
    cudaGetSymbolAddress((void**)&hl,   g_hl);
    cudaGetSymbolAddress((void**)&y,    g_y);

    cudaFuncSetAttribute(moe_gemm1, cudaFuncAttributeMaxDynamicSharedMemorySize, 131072);
    cudaFuncSetAttribute(moe_gemm2, cudaFuncAttributeMaxDynamicSharedMemorySize, 98304);

    init_kernel  <<<1, 32>>>();
    router_kernel<<<T_ / 256, 256>>>(logits);

    split_kernel  <<<(T_ * H_ / 4 + 255) / 256, 256>>>(x, xh, xl, (size_t)T_ * H_ / 4);
    convert_kernel<<<((size_t)E_ * 2 * I_ * H_ / 4 + 255) / 256, 256>>>(
        w13, w13h, (size_t)E_ * 2 * I_ * H_ / 4);
    convert_kernel<<<((size_t)E_ * H_ * I_ / 4 + 255) / 256, 256>>>(
        w2, w2h, (size_t)E_ * H_ * I_ / 4);

    // GEMM1: 128x256 tile, gate/up interleave folded into B addressing
    moe_gemm1<<<dim3(2 * I_ / 256, CAP / 128, E_), 256, 131072>>>(xh, xl, w13h, hh, hl);

    // GEMM2: dual-pass (hh + hl), 128x128 tile
    moe_gemm2<<<dim3(H_ / 128, CAP / 128, E_), 256, 98304>>>(hh, hl, w2h, y);

    combine_kernel<<<T_, 256>>>(out);
}